// round 3
// baseline (speedup 1.0000x reference)
#include <cuda_runtime.h>
#include <math.h>

// Problem constants (N,D,C,E,K = 100000,64,40,1600000,2)
#define NN 100000
#define DD 64
#define CC 40
#define EE 1600000
#define NBLK_SCAN ((NN + 1023) / 1024)   // 98

// ---- device scratch (__device__ globals; allocation APIs are banned) ----
__device__ int    g_mode;                 // 64 if edge_index is int64, else 32
__device__ int    g_deg[NN];
__device__ float  g_dis[NN];
__device__ int    g_rowptr[NN + 1];
__device__ int    g_cursor[NN];
__device__ int    g_col[EE];
__device__ int    g_bsums[NBLK_SCAN + 1];
__device__ float2 g_buf0[(size_t)NN * (DD / 2)];   // hop-1 output, 8B-aligned by type

// ---------------------------------------------------------------------
// 0) detect edge_index dtype: int64 values must all be in [0, N)
// ---------------------------------------------------------------------
__global__ void k_detect(const long long* __restrict__ ei) {
    if (threadIdx.x == 0 && blockIdx.x == 0) {
        int bad = 0;
        for (int i = 0; i < 256; i++) {
            long long v = ei[i];
            if (v < 0 || v >= NN) { bad = 1; break; }
        }
        g_mode = bad ? 32 : 64;
    }
}

__device__ __forceinline__ int edge_at(const void* ei, long long idx, int mode) {
    if (mode == 64) return (int)((const long long*)ei)[idx];
    return ((const int*)ei)[idx];
}

// ---------------------------------------------------------------------
// 1) degree: deg[i] = 1 (self loop) + count of edge rows == i
// ---------------------------------------------------------------------
__global__ void k_init_deg(int n) {
    int i = blockIdx.x * blockDim.x + threadIdx.x;
    if (i < n) g_deg[i] = 1;
}

__global__ void k_count_deg(const void* __restrict__ ei, int e) {
    int i = blockIdx.x * blockDim.x + threadIdx.x;
    if (i < e) {
        int r = edge_at(ei, i, g_mode);
        atomicAdd(&g_deg[r], 1);
    }
}

__global__ void k_dis(int n) {
    int i = blockIdx.x * blockDim.x + threadIdx.x;
    if (i < n) g_dis[i] = rsqrtf((float)g_deg[i]);
}

// ---------------------------------------------------------------------
// 2) CSR build: exclusive scan of counts (deg-1), then scatter cols
// ---------------------------------------------------------------------
__global__ void k_scan_block(int n) {
    __shared__ int sh[1024];
    int i = blockIdx.x * 1024 + threadIdx.x;
    int v = (i < n) ? (g_deg[i] - 1) : 0;
    sh[threadIdx.x] = v;
    __syncthreads();
    #pragma unroll
    for (int off = 1; off < 1024; off <<= 1) {
        int t = (threadIdx.x >= off) ? sh[threadIdx.x - off] : 0;
        __syncthreads();
        sh[threadIdx.x] += t;
        __syncthreads();
    }
    int incl = sh[threadIdx.x];
    if (i < n) g_rowptr[i] = incl - v;
    if (threadIdx.x == 1023) g_bsums[blockIdx.x] = incl;
}

__global__ void k_scan_bsums(int nb) {
    if (threadIdx.x == 0 && blockIdx.x == 0) {
        int acc = 0;
        for (int i = 0; i < nb; i++) { int v = g_bsums[i]; g_bsums[i] = acc; acc += v; }
    }
}

__global__ void k_scan_apply(int n, int e) {
    int i = blockIdx.x * 1024 + threadIdx.x;
    if (i < n) {
        int p = g_rowptr[i] + g_bsums[blockIdx.x];
        g_rowptr[i] = p;
        g_cursor[i] = p;
        if (i == n - 1) g_rowptr[n] = e;
    }
}

__global__ void k_fill(const void* __restrict__ ei, int e) {
    int i = blockIdx.x * blockDim.x + threadIdx.x;
    if (i < e) {
        int m = g_mode;
        int r = edge_at(ei, i, m);
        int c = edge_at(ei, (long long)e + i, m);
        int pos = atomicAdd(&g_cursor[r], 1);
        g_col[pos] = c;
    }
}

// ---------------------------------------------------------------------
// 3) hop 1: g_buf0[r] = dis[r]*sum_c dis[c]*x[c] + dis[r]^2*x[r]
//    warp per row, float2 per lane
// ---------------------------------------------------------------------
__global__ void __launch_bounds__(256)
k_prop1(const float* __restrict__ x, int n) {
    int warp = (blockIdx.x * blockDim.x + threadIdx.x) >> 5;
    int lane = threadIdx.x & 31;
    if (warp >= n) return;
    int beg = g_rowptr[warp];
    int end = g_rowptr[warp + 1];
    float accx = 0.f, accy = 0.f;
    int e = beg;
    for (; e + 1 < end; e += 2) {
        int c0 = g_col[e];
        int c1 = g_col[e + 1];
        float w0 = g_dis[c0];
        float w1 = g_dis[c1];
        float2 v0 = *(const float2*)(x + (size_t)c0 * DD + lane * 2);
        float2 v1 = *(const float2*)(x + (size_t)c1 * DD + lane * 2);
        accx += w0 * v0.x + w1 * v1.x;
        accy += w0 * v0.y + w1 * v1.y;
    }
    if (e < end) {
        int c0 = g_col[e];
        float w0 = g_dis[c0];
        float2 v0 = *(const float2*)(x + (size_t)c0 * DD + lane * 2);
        accx += w0 * v0.x;
        accy += w0 * v0.y;
    }
    float dr = g_dis[warp];
    float sl = dr * dr;
    float2 xs = *(const float2*)(x + (size_t)warp * DD + lane * 2);
    float2 o;
    o.x = dr * accx + sl * xs.x;
    o.y = dr * accy + sl * xs.y;
    g_buf0[(size_t)warp * (DD / 2) + lane] = o;
}

// ---------------------------------------------------------------------
// 4) fused hop 2 + GEMM + log_softmax
//    h[r] = dis[r]*sum_c dis[c]*buf0[c] + dis[r]^2*buf0[r]   (in registers)
//    logits = h @ W + b ; out = log_softmax(logits)
// ---------------------------------------------------------------------
__global__ void __launch_bounds__(256)
k_prop2_gemm(const float* __restrict__ W, const float* __restrict__ b,
             float* __restrict__ out, int n) {
    __shared__ float Ws[DD * CC];
    __shared__ float bs[CC];
    for (int i = threadIdx.x; i < DD * CC; i += blockDim.x) Ws[i] = W[i];
    for (int i = threadIdx.x; i < CC; i += blockDim.x) bs[i] = b[i];
    __syncthreads();

    int warp = (blockIdx.x * blockDim.x + threadIdx.x) >> 5;
    int lane = threadIdx.x & 31;
    if (warp >= n) return;

    // ---- hop 2 (gather) ----
    int beg = g_rowptr[warp];
    int end = g_rowptr[warp + 1];
    float accx = 0.f, accy = 0.f;
    int e = beg;
    for (; e + 1 < end; e += 2) {
        int c0 = g_col[e];
        int c1 = g_col[e + 1];
        float w0 = g_dis[c0];
        float w1 = g_dis[c1];
        float2 v0 = g_buf0[(size_t)c0 * (DD / 2) + lane];
        float2 v1 = g_buf0[(size_t)c1 * (DD / 2) + lane];
        accx += w0 * v0.x + w1 * v1.x;
        accy += w0 * v0.y + w1 * v1.y;
    }
    if (e < end) {
        int c0 = g_col[e];
        float w0 = g_dis[c0];
        float2 v0 = g_buf0[(size_t)c0 * (DD / 2) + lane];
        accx += w0 * v0.x;
        accy += w0 * v0.y;
    }
    float dr = g_dis[warp];
    float sl = dr * dr;
    float2 xs = g_buf0[(size_t)warp * (DD / 2) + lane];
    float hx = dr * accx + sl * xs.x;   // feature 2*lane
    float hy = dr * accy + sl * xs.y;   // feature 2*lane+1

    // ---- GEMM: lane owns output cols {lane, lane+32(if<40)} ----
    float acc0 = bs[lane];
    float acc1 = (lane < CC - 32) ? bs[lane + 32] : 0.f;
    #pragma unroll
    for (int k = 0; k < DD; k++) {
        float xk = __shfl_sync(0xFFFFFFFFu, (k & 1) ? hy : hx, k >> 1);
        acc0 += xk * Ws[k * CC + lane];
        if (lane < CC - 32) acc1 += xk * Ws[k * CC + lane + 32];
    }

    // ---- log_softmax over 40 logits ----
    float m = acc0;
    if (lane < CC - 32) m = fmaxf(m, acc1);
    #pragma unroll
    for (int off = 16; off; off >>= 1)
        m = fmaxf(m, __shfl_xor_sync(0xFFFFFFFFu, m, off));

    float s = __expf(acc0 - m);
    if (lane < CC - 32) s += __expf(acc1 - m);
    #pragma unroll
    for (int off = 16; off; off >>= 1)
        s += __shfl_xor_sync(0xFFFFFFFFu, s, off);

    float lse = m + __logf(s);
    out[(size_t)warp * CC + lane] = acc0 - lse;
    if (lane < CC - 32) out[(size_t)warp * CC + lane + 32] = acc1 - lse;
}

// ---------------------------------------------------------------------
extern "C" void kernel_launch(void* const* d_in, const int* in_sizes, int n_in,
                              void* d_out, int out_size) {
    const float* x  = (const float*)d_in[0];
    const void*  ei = (const void*)d_in[1];
    const float* W  = (const float*)d_in[2];
    const float* b  = (const float*)d_in[3];
    float* out = (float*)d_out;

    const int n = NN, e = EE;
    const int T = 256;

    k_detect    <<<1, 32>>>((const long long*)ei);
    k_init_deg  <<<(n + T - 1) / T, T>>>(n);
    k_count_deg <<<(e + T - 1) / T, T>>>(ei, e);
    k_dis       <<<(n + T - 1) / T, T>>>(n);
    k_scan_block<<<NBLK_SCAN, 1024>>>(n);
    k_scan_bsums<<<1, 32>>>(NBLK_SCAN);
    k_scan_apply<<<NBLK_SCAN, 1024>>>(n, e);
    k_fill      <<<(e + T - 1) / T, T>>>(ei, e);

    int prop_blocks = (n * 32 + T - 1) / T;   // warp per row
    k_prop1     <<<prop_blocks, T>>>(x, n);
    k_prop2_gemm<<<prop_blocks, T>>>(W, b, out, n);
}

// round 4
// speedup vs baseline: 1.0309x; 1.0309x over previous
#include <cuda_runtime.h>
#include <math.h>

// Problem constants (N,D,C,E,K = 100000,64,40,1600000,2)
#define NN 100000
#define DD 64
#define CC 40
#define EE 1600000
#define NBLK_SCAN ((NN + 1023) / 1024)   // 98

// ---- device scratch (__device__ globals; allocation APIs are banned) ----
__device__ int    g_mode;                 // 64 if edge_index is int64, else 32
__device__ int    g_deg[NN];
__device__ float  g_dis[NN];
__device__ int    g_rowptr[NN + 1];
__device__ int    g_cursor[NN];
__device__ int    g_col[EE];
__device__ int    g_bsums[NBLK_SCAN + 1];
__device__ float2 g_buf0[(size_t)NN * (DD / 2)];   // hop-1 output

// ---------------------------------------------------------------------
// 0) detect edge_index dtype (int64 values must be in [0,N)) + init deg=1
// ---------------------------------------------------------------------
__global__ void k_detect_init(const long long* __restrict__ ei, int n) {
    int i = blockIdx.x * blockDim.x + threadIdx.x;
    if (i < n) g_deg[i] = 1;
    if (blockIdx.x == 0 && threadIdx.x < 32) {
        int bad = 0;
        for (int k = threadIdx.x; k < 256; k += 32) {
            long long v = ei[k];
            if (v < 0 || v >= NN) bad = 1;
        }
        unsigned ball = __ballot_sync(0xFFFFFFFFu, bad);
        if (threadIdx.x == 0) g_mode = ball ? 32 : 64;
    }
}

// ---------------------------------------------------------------------
// 1) degree count over edge rows (2 edges per thread, vectorized)
// ---------------------------------------------------------------------
__global__ void k_count_deg(const void* __restrict__ ei, int e) {
    int i = blockIdx.x * blockDim.x + threadIdx.x;   // pair index
    int base = i * 2;
    if (base >= e) return;
    int r0, r1 = -1;
    if (g_mode == 64) {
        longlong2 v = ((const longlong2*)ei)[i];
        r0 = (int)v.x; if (base + 1 < e) r1 = (int)v.y;
    } else {
        int2 v = ((const int2*)ei)[i];
        r0 = v.x; if (base + 1 < e) r1 = v.y;
    }
    atomicAdd(&g_deg[r0], 1);
    if (r1 >= 0) atomicAdd(&g_deg[r1], 1);
}

// ---------------------------------------------------------------------
// 2) CSR build: block scan -> warp scan of block sums -> apply (+dis,cursor)
// ---------------------------------------------------------------------
__global__ void k_scan_block(int n) {
    __shared__ int sh[1024];
    int i = blockIdx.x * 1024 + threadIdx.x;
    int v = (i < n) ? (g_deg[i] - 1) : 0;
    sh[threadIdx.x] = v;
    __syncthreads();
    #pragma unroll
    for (int off = 1; off < 1024; off <<= 1) {
        int t = (threadIdx.x >= off) ? sh[threadIdx.x - off] : 0;
        __syncthreads();
        sh[threadIdx.x] += t;
        __syncthreads();
    }
    int incl = sh[threadIdx.x];
    if (i < n) g_rowptr[i] = incl - v;
    if (threadIdx.x == 1023) g_bsums[blockIdx.x] = incl;
}

__global__ void k_scan_bsums(int nb) {   // one warp, shfl scan in chunks of 32
    int lane = threadIdx.x;
    int carry = 0;
    for (int base = 0; base < nb; base += 32) {
        int idx = base + lane;
        int orig = (idx < nb) ? g_bsums[idx] : 0;
        int v = orig;
        #pragma unroll
        for (int o = 1; o < 32; o <<= 1) {
            int t = __shfl_up_sync(0xFFFFFFFFu, v, o);
            if (lane >= o) v += t;
        }
        if (idx < nb) g_bsums[idx] = (v - orig) + carry;   // exclusive + carry
        carry += __shfl_sync(0xFFFFFFFFu, v, 31);
    }
}

__global__ void k_scan_apply(int n, int e) {
    int i = blockIdx.x * 1024 + threadIdx.x;
    if (i < n) {
        int p = g_rowptr[i] + g_bsums[blockIdx.x];
        g_rowptr[i] = p;
        g_cursor[i] = p;
        g_dis[i] = rsqrtf((float)g_deg[i]);
        if (i == n - 1) g_rowptr[n] = e;
    }
}

// ---------------------------------------------------------------------
// 3) fill CSR cols (2 edges per thread, vectorized reads)
// ---------------------------------------------------------------------
__global__ void k_fill(const void* __restrict__ ei, int e) {
    int i = blockIdx.x * blockDim.x + threadIdx.x;   // pair index
    int base = i * 2;
    if (base >= e) return;
    int r0, c0, r1 = -1, c1 = 0;
    int epairs = e / 2;                               // E even
    if (g_mode == 64) {
        longlong2 rv = ((const longlong2*)ei)[i];
        longlong2 cv = ((const longlong2*)ei)[epairs + i];
        r0 = (int)rv.x; c0 = (int)cv.x;
        if (base + 1 < e) { r1 = (int)rv.y; c1 = (int)cv.y; }
    } else {
        int2 rv = ((const int2*)ei)[i];
        int2 cv = ((const int2*)ei)[epairs + i];
        r0 = rv.x; c0 = cv.x;
        if (base + 1 < e) { r1 = rv.y; c1 = cv.y; }
    }
    int p0 = atomicAdd(&g_cursor[r0], 1);
    g_col[p0] = c0;
    if (r1 >= 0) {
        int p1 = atomicAdd(&g_cursor[r1], 1);
        g_col[p1] = c1;
    }
}

// ---------------------------------------------------------------------
// 4) hop 1: warp per row, lane-parallel (col,dis) staging + 4-edge unroll
//    g_buf0[r] = dis[r]*sum_c dis[c]*x[c] + dis[r]^2*x[r]
// ---------------------------------------------------------------------
__global__ void __launch_bounds__(256)
k_prop1(const float* __restrict__ x, int n) {
    int warp = (blockIdx.x * blockDim.x + threadIdx.x) >> 5;
    int lane = threadIdx.x & 31;
    if (warp >= n) return;
    int beg = g_rowptr[warp];
    int end = g_rowptr[warp + 1];
    float accx = 0.f, accy = 0.f;

    for (int base = beg; base < end; base += 32) {
        int m = end - base; if (m > 32) m = 32;
        int   c = 0; float w = 0.f;
        if (lane < m) { c = g_col[base + lane]; w = g_dis[c]; }
        int j = 0;
        for (; j + 4 <= m; j += 4) {
            int   c0 = __shfl_sync(0xFFFFFFFFu, c, j);
            int   c1 = __shfl_sync(0xFFFFFFFFu, c, j + 1);
            int   c2 = __shfl_sync(0xFFFFFFFFu, c, j + 2);
            int   c3 = __shfl_sync(0xFFFFFFFFu, c, j + 3);
            float w0 = __shfl_sync(0xFFFFFFFFu, w, j);
            float w1 = __shfl_sync(0xFFFFFFFFu, w, j + 1);
            float w2 = __shfl_sync(0xFFFFFFFFu, w, j + 2);
            float w3 = __shfl_sync(0xFFFFFFFFu, w, j + 3);
            float2 v0 = *(const float2*)(x + (size_t)c0 * DD + lane * 2);
            float2 v1 = *(const float2*)(x + (size_t)c1 * DD + lane * 2);
            float2 v2 = *(const float2*)(x + (size_t)c2 * DD + lane * 2);
            float2 v3 = *(const float2*)(x + (size_t)c3 * DD + lane * 2);
            accx += w0 * v0.x + w1 * v1.x + w2 * v2.x + w3 * v3.x;
            accy += w0 * v0.y + w1 * v1.y + w2 * v2.y + w3 * v3.y;
        }
        for (; j < m; j++) {
            int   c0 = __shfl_sync(0xFFFFFFFFu, c, j);
            float w0 = __shfl_sync(0xFFFFFFFFu, w, j);
            float2 v0 = *(const float2*)(x + (size_t)c0 * DD + lane * 2);
            accx += w0 * v0.x;
            accy += w0 * v0.y;
        }
    }
    float dr = g_dis[warp];
    float sl = dr * dr;
    float2 xs = *(const float2*)(x + (size_t)warp * DD + lane * 2);
    float2 o;
    o.x = dr * accx + sl * xs.x;
    o.y = dr * accy + sl * xs.y;
    g_buf0[(size_t)warp * (DD / 2) + lane] = o;
}

// ---------------------------------------------------------------------
// 5) fused hop 2 + GEMM + log_softmax (same staging scheme)
// ---------------------------------------------------------------------
__global__ void __launch_bounds__(256)
k_prop2_gemm(const float* __restrict__ W, const float* __restrict__ b,
             float* __restrict__ out, int n) {
    __shared__ float Ws[DD * CC];
    __shared__ float bs[CC];
    for (int i = threadIdx.x; i < DD * CC; i += blockDim.x) Ws[i] = W[i];
    for (int i = threadIdx.x; i < CC; i += blockDim.x) bs[i] = b[i];
    __syncthreads();

    int warp = (blockIdx.x * blockDim.x + threadIdx.x) >> 5;
    int lane = threadIdx.x & 31;
    if (warp >= n) return;

    // ---- hop 2 (gather from g_buf0) ----
    int beg = g_rowptr[warp];
    int end = g_rowptr[warp + 1];
    float accx = 0.f, accy = 0.f;
    for (int base = beg; base < end; base += 32) {
        int m = end - base; if (m > 32) m = 32;
        int   c = 0; float w = 0.f;
        if (lane < m) { c = g_col[base + lane]; w = g_dis[c]; }
        int j = 0;
        for (; j + 4 <= m; j += 4) {
            int   c0 = __shfl_sync(0xFFFFFFFFu, c, j);
            int   c1 = __shfl_sync(0xFFFFFFFFu, c, j + 1);
            int   c2 = __shfl_sync(0xFFFFFFFFu, c, j + 2);
            int   c3 = __shfl_sync(0xFFFFFFFFu, c, j + 3);
            float w0 = __shfl_sync(0xFFFFFFFFu, w, j);
            float w1 = __shfl_sync(0xFFFFFFFFu, w, j + 1);
            float w2 = __shfl_sync(0xFFFFFFFFu, w, j + 2);
            float w3 = __shfl_sync(0xFFFFFFFFu, w, j + 3);
            float2 v0 = g_buf0[(size_t)c0 * (DD / 2) + lane];
            float2 v1 = g_buf0[(size_t)c1 * (DD / 2) + lane];
            float2 v2 = g_buf0[(size_t)c2 * (DD / 2) + lane];
            float2 v3 = g_buf0[(size_t)c3 * (DD / 2) + lane];
            accx += w0 * v0.x + w1 * v1.x + w2 * v2.x + w3 * v3.x;
            accy += w0 * v0.y + w1 * v1.y + w2 * v2.y + w3 * v3.y;
        }
        for (; j < m; j++) {
            int   c0 = __shfl_sync(0xFFFFFFFFu, c, j);
            float w0 = __shfl_sync(0xFFFFFFFFu, w, j);
            float2 v0 = g_buf0[(size_t)c0 * (DD / 2) + lane];
            accx += w0 * v0.x;
            accy += w0 * v0.y;
        }
    }
    float dr = g_dis[warp];
    float sl = dr * dr;
    float2 xs = g_buf0[(size_t)warp * (DD / 2) + lane];
    float hx = dr * accx + sl * xs.x;   // feature 2*lane
    float hy = dr * accy + sl * xs.y;   // feature 2*lane+1

    // ---- GEMM: lane owns output cols {lane, lane+32(if<40)} ----
    float acc0 = bs[lane];
    float acc1 = (lane < CC - 32) ? bs[lane + 32] : 0.f;
    #pragma unroll
    for (int k = 0; k < DD; k++) {
        float xk = __shfl_sync(0xFFFFFFFFu, (k & 1) ? hy : hx, k >> 1);
        acc0 += xk * Ws[k * CC + lane];
        if (lane < CC - 32) acc1 += xk * Ws[k * CC + lane + 32];
    }

    // ---- log_softmax over 40 logits ----
    float m = acc0;
    if (lane < CC - 32) m = fmaxf(m, acc1);
    #pragma unroll
    for (int off = 16; off; off >>= 1)
        m = fmaxf(m, __shfl_xor_sync(0xFFFFFFFFu, m, off));

    float s = __expf(acc0 - m);
    if (lane < CC - 32) s += __expf(acc1 - m);
    #pragma unroll
    for (int off = 16; off; off >>= 1)
        s += __shfl_xor_sync(0xFFFFFFFFu, s, off);

    float lse = m + __logf(s);
    out[(size_t)warp * CC + lane] = acc0 - lse;
    if (lane < CC - 32) out[(size_t)warp * CC + lane + 32] = acc1 - lse;
}

// ---------------------------------------------------------------------
extern "C" void kernel_launch(void* const* d_in, const int* in_sizes, int n_in,
                              void* d_out, int out_size) {
    const float* x  = (const float*)d_in[0];
    const void*  ei = (const void*)d_in[1];
    const float* W  = (const float*)d_in[2];
    const float* b  = (const float*)d_in[3];
    float* out = (float*)d_out;

    const int n = NN, e = EE;
    const int T = 256;

    k_detect_init<<<(n + T - 1) / T, T>>>((const long long*)ei, n);
    k_count_deg  <<<(e / 2 + T - 1) / T, T>>>(ei, e);
    k_scan_block <<<NBLK_SCAN, 1024>>>(n);
    k_scan_bsums <<<1, 32>>>(NBLK_SCAN);
    k_scan_apply <<<NBLK_SCAN, 1024>>>(n, e);
    k_fill       <<<(e / 2 + T - 1) / T, T>>>(ei, e);

    int prop_blocks = (n * 32 + T - 1) / T;   // warp per row
    k_prop1      <<<prop_blocks, T>>>(x, n);
    k_prop2_gemm <<<prop_blocks, T>>>(W, b, out, n);
}